// round 7
// baseline (speedup 1.0000x reference)
#include <cuda_runtime.h>

// ---------------- problem constants ----------------
#define NB    32          // batch
#define CC    128         // cell channels
#define CIN   512         // input channels
#define HW    1024        // 32*32
#define PLANE (CC*HW)     // 131072 floats per (batch, state)
#define NBPLANE (NB*PLANE)
#define NMIX  14
#define BNS   0.9999950000374997f   // 1/sqrt(1+1e-5)

typedef unsigned long long ull;

// ---------------- device scratch (static, allocation-free) ----------------
__device__ __align__(16) float g_s0[NBPLANE];
__device__ __align__(16) float g_s1[NBPLANE];
__device__ __align__(16) float g_t[20L * NBPLANE];   // dw1 outputs (and dw2 outputs, aliased)
__device__ __align__(16) float g_u[10L * NBPLANE];   // sep pw1 outputs
__device__ __align__(16) float g_pw[NMIX * NB * 8];

// ---------------- packed f32x2 helpers ----------------
__device__ __forceinline__ void ffma2(ull& d, ull a, ull b) {
    asm("fma.rn.f32x2 %0, %1, %2, %0;" : "+l"(d) : "l"(a), "l"(b));
}
__device__ __forceinline__ ull pack2(float x) {
    ull r;
    asm("mov.b64 %0, {%1, %1};" : "=l"(r) : "f"(x));
    return r;
}
__device__ __forceinline__ float2 unpack2(ull v) {
    float2 f;
    asm("mov.b64 {%0, %1}, %2;" : "=f"(f.x), "=f"(f.y) : "l"(v));
    return f;
}

// ---------------- gate kernel: top-2 + masked softmax ----------------
__global__ void gate_kernel(const float* __restrict__ gates, float* __restrict__ P) {
    int idx = blockIdx.x * blockDim.x + threadIdx.x;
    if (idx >= NMIX * NB) return;
    const float* g = gates + idx * 8;
    float gv[8];
#pragma unroll
    for (int j = 0; j < 8; j++) gv[j] = g[j];
    bool sel[8] = {false, false, false, false, false, false, false, false};
    for (int t = 0; t < 2; t++) {      // top = 2 fixed by setup_inputs
        int best = -1; float bv = -3.4e38f;
#pragma unroll
        for (int j = 0; j < 8; j++)
            if (!sel[j] && gv[j] > bv) { bv = gv[j]; best = j; }
        sel[best] = true;
    }
    float mx = -3.4e38f;
#pragma unroll
    for (int j = 0; j < 8; j++) if (sel[j]) mx = fmaxf(mx, gv[j]);
    float e[8]; float s = 0.f;
#pragma unroll
    for (int j = 0; j < 8; j++) { e[j] = sel[j] ? expf(gv[j] - mx) : 0.f; s += e[j]; }
#pragma unroll
    for (int j = 0; j < 8; j++) P[idx * 8 + j] = e[j] / s;
}

// ---------------- fused pool/skip kernel (loops over all j of a step) ----------------
struct PoolArgs {
    const float* X[5]; long bsX[5];
    const float* P[5];
    float* O; long bsO;
    int nj;
};

__global__ __launch_bounds__(256) void pool_kernel(PoolArgs pa) {
    int c = blockIdx.x, b = blockIdx.y, tid = threadIdx.x;
    __shared__ float st[1024];
    float acc[4] = {0.f, 0.f, 0.f, 0.f};
    for (int j = 0; j < pa.nj; j++) {
        const float* pj = pa.P[j] + b * 8;
        float p1 = pj[1], p2 = pj[2], p3 = pj[3];
        if (p1 == 0.f && p2 == 0.f && p3 == 0.f) continue;   // uniform over block
        __syncthreads();
        const float* xp = pa.X[j] + (long)b * pa.bsX[j] + c * HW;
        for (int i = tid; i < 1024; i += 256) st[i] = xp[i];
        __syncthreads();
#pragma unroll
        for (int q = 0; q < 4; q++) {
            int px = tid + q * 256;
            int y = px >> 5, x = px & 31;
            float mx = -3.4e38f, s = 0.f; int cnt = 0;
#pragma unroll
            for (int dy = -1; dy <= 1; dy++) {
                int yy = y + dy;
                if (yy < 0 || yy > 31) continue;
#pragma unroll
                for (int dx = -1; dx <= 1; dx++) {
                    int xx = x + dx;
                    if (xx < 0 || xx > 31) continue;
                    float v = st[yy * 32 + xx];
                    mx = fmaxf(mx, v); s += v; cnt++;
                }
            }
            acc[q] += p1 * (BNS * mx) + p2 * (BNS * (s / (float)cnt)) + p3 * st[px];
        }
    }
    float* op = pa.O + (long)b * pa.bsO + c * HW;
#pragma unroll
    for (int q = 0; q < 4; q++) op[tid + q * 256] = acc[q];   // sole writer pre-GEMM
}

// ---------------- fused multi-entry depthwise conv ----------------
struct DwArgs {
    const float* X[20]; long bsX[20];
    const float* W[20];
    float*       Y[20];
    const float* P[20];
    int ks[20], dil[20];
};

template<int KS, int DIL, int PAD>
__device__ __forceinline__ void dw_inner(const float* __restrict__ st,
                                         const float* __restrict__ w,
                                         float* __restrict__ yp, int tid)
{
    for (int px = tid; px < 1024; px += 256) {
        int y = px >> 5, x = px & 31;
        const float* base = st + (y + 4 - PAD) * 40 + (x + 4 - PAD);
        float acc = 0.f;
#pragma unroll
        for (int i = 0; i < KS; i++)
#pragma unroll
            for (int j = 0; j < KS; j++)
                acc += w[i * KS + j] * base[i * DIL * 40 + j * DIL];
        yp[px] = acc;
    }
}

__global__ __launch_bounds__(256) void dw_kernel(DwArgs da) {
    int e = blockIdx.z, b = blockIdx.y, c = blockIdx.x;
    if (da.P[e][b * 8] == 0.f) return;
    __shared__ float st[1600];  // 40x40, relu(x) with zero halo (max pad 4)
    int tid = threadIdx.x;
    for (int i = tid; i < 1600; i += 256) st[i] = 0.f;
    __syncthreads();
    const float* xp = da.X[e] + (long)b * da.bsX[e] + c * HW;
    for (int i = tid; i < 1024; i += 256) {
        int y = i >> 5, x = i & 31;
        st[(y + 4) * 40 + x + 4] = fmaxf(xp[i], 0.f);
    }
    __syncthreads();
    int ks = da.ks[e];
    int ksz = ks * ks;
    const float* wp = da.W[e] + c * ksz;
    float w[25];
#pragma unroll
    for (int i = 0; i < 25; i++) w[i] = (i < ksz) ? wp[i] : 0.f;
    float* yp = da.Y[e] + (long)b * PLANE + c * HW;
    int dil = da.dil[e];
    if (ks == 3 && dil == 1)      dw_inner<3,1,1>(st, w, yp, tid);
    else if (ks == 5 && dil == 1) dw_inner<5,1,2>(st, w, yp, tid);
    else if (ks == 3)             dw_inner<3,2,2>(st, w, yp, tid);
    else                          dw_inner<5,2,4>(st, w, yp, tid);
}

// ---------------- fused multi-entry GEMM, FFMA2 (f32x2) ----------------
// block tile: 128(M) x 256(N); thread tile 8(M) x 16(N) packed as 8 f32x2.
struct GemmArgs {
    const float* A[20];
    const float* B[20];
    float*       Cp[20];
    const float* P[20];
    float        cscale[20];
    int          byP[20];
    int          accum[20];
    long         bsB[20];
    long         bsC[20];
    int          K;
    int          reluB;
};

__device__ __forceinline__ void relu4(float4& v) {
    v.x = fmaxf(v.x, 0.f); v.y = fmaxf(v.y, 0.f);
    v.z = fmaxf(v.z, 0.f); v.w = fmaxf(v.w, 0.f);
}

__global__ __launch_bounds__(256) void gemm256(GemmArgs ga) {
    int e = blockIdx.z, b = blockIdx.y;
    const float* gp = ga.P[e];
    float pv = 1.f;
    if (gp) { pv = gp[b * 8]; if (pv == 0.f) return; }
    float scale = ga.cscale[e] * (ga.byP[e] ? pv : 1.f);
    const int K = ga.K;
    const int reluB = ga.reluB;

    __shared__ float As[2][16][128];
    __shared__ float Bs[2][16][256];

    int tid  = threadIdx.x;
    int arow = tid >> 1,  akoff = (tid & 1) * 8;      // A loader: 8 k-floats of row arow
    int bk   = tid >> 4,  bcol = (tid & 15) * 16;     // B loader: 16 n-floats of k-row bk
    int tm   = tid >> 4,  tn   = tid & 15;            // compute mapping

    const float* Aptr = ga.A[e] + (long)arow * K + akoff;
    const float* Bptr = ga.B[e] + (long)b * ga.bsB[e] + blockIdx.x * 256
                        + (long)bk * HW + bcol;
    float* Cm = ga.Cp[e] + (long)b * ga.bsC[e] + blockIdx.x * 256;

    ull acc[8][8];
#pragma unroll
    for (int i = 0; i < 8; i++)
#pragma unroll
        for (int j = 0; j < 8; j++) acc[i][j] = 0ull;

    // prologue: tile 0 -> buffer 0
    {
        float4 a0 = *(const float4*)(Aptr);
        float4 a1 = *(const float4*)(Aptr + 4);
        float4 b0 = *(const float4*)(Bptr);
        float4 b1 = *(const float4*)(Bptr + 4);
        float4 b2 = *(const float4*)(Bptr + 8);
        float4 b3 = *(const float4*)(Bptr + 12);
        if (reluB) { relu4(b0); relu4(b1); relu4(b2); relu4(b3); }
        As[0][akoff + 0][arow] = a0.x; As[0][akoff + 1][arow] = a0.y;
        As[0][akoff + 2][arow] = a0.z; As[0][akoff + 3][arow] = a0.w;
        As[0][akoff + 4][arow] = a1.x; As[0][akoff + 5][arow] = a1.y;
        As[0][akoff + 6][arow] = a1.z; As[0][akoff + 7][arow] = a1.w;
        *(float4*)&Bs[0][bk][bcol + 0]  = b0;
        *(float4*)&Bs[0][bk][bcol + 4]  = b1;
        *(float4*)&Bs[0][bk][bcol + 8]  = b2;
        *(float4*)&Bs[0][bk][bcol + 12] = b3;
    }

    const int T = K >> 4;
    int cur = 0;
    for (int t = 0; t < T; t++) {
        __syncthreads();
        float4 na0, na1, nb0, nb1, nb2, nb3;
        bool more = (t + 1 < T);
        if (more) {
            na0 = *(const float4*)(Aptr + (t + 1) * 16);
            na1 = *(const float4*)(Aptr + (t + 1) * 16 + 4);
            const float* bp = Bptr + (long)(t + 1) * 16 * HW;
            nb0 = *(const float4*)(bp);
            nb1 = *(const float4*)(bp + 4);
            nb2 = *(const float4*)(bp + 8);
            nb3 = *(const float4*)(bp + 12);
        }
#pragma unroll
        for (int kk = 0; kk < 16; kk++) {
            ull bb[8];
            const ull* bp2 = (const ull*)&Bs[cur][kk][tn * 16];
#pragma unroll
            for (int q = 0; q < 8; q++) bb[q] = bp2[q];
            float4 a0 = *(const float4*)&As[cur][kk][tm * 8];
            float4 a1 = *(const float4*)&As[cur][kk][tm * 8 + 4];
            float av[8] = {a0.x, a0.y, a0.z, a0.w, a1.x, a1.y, a1.z, a1.w};
#pragma unroll
            for (int i = 0; i < 8; i++) {
                ull a2 = pack2(av[i]);
#pragma unroll
                for (int j = 0; j < 8; j++)
                    ffma2(acc[i][j], a2, bb[j]);
            }
        }
        if (more) {
            if (reluB) { relu4(nb0); relu4(nb1); relu4(nb2); relu4(nb3); }
            int nxt = cur ^ 1;
            As[nxt][akoff + 0][arow] = na0.x; As[nxt][akoff + 1][arow] = na0.y;
            As[nxt][akoff + 2][arow] = na0.z; As[nxt][akoff + 3][arow] = na0.w;
            As[nxt][akoff + 4][arow] = na1.x; As[nxt][akoff + 5][arow] = na1.y;
            As[nxt][akoff + 6][arow] = na1.z; As[nxt][akoff + 7][arow] = na1.w;
            *(float4*)&Bs[nxt][bk][bcol + 0]  = nb0;
            *(float4*)&Bs[nxt][bk][bcol + 4]  = nb1;
            *(float4*)&Bs[nxt][bk][bcol + 8]  = nb2;
            *(float4*)&Bs[nxt][bk][bcol + 12] = nb3;
            cur = nxt;
        }
    }

    if (ga.accum[e]) {
#pragma unroll
        for (int i = 0; i < 8; i++) {
            float* crow = Cm + (long)(tm * 8 + i) * HW + tn * 16;
#pragma unroll
            for (int j = 0; j < 8; j++) {
                float2 v = unpack2(acc[i][j]);
                atomicAdd(&crow[2 * j],     scale * v.x);
                atomicAdd(&crow[2 * j + 1], scale * v.y);
            }
        }
    } else {
#pragma unroll
        for (int i = 0; i < 8; i++) {
            float* crow = Cm + (long)(tm * 8 + i) * HW + tn * 16;
#pragma unroll
            for (int q = 0; q < 4; q++) {
                float2 v0 = unpack2(acc[i][2 * q]);
                float2 v1 = unpack2(acc[i][2 * q + 1]);
                float4 o = make_float4(scale * v0.x, scale * v0.y,
                                       scale * v1.x, scale * v1.y);
                *(float4*)&crow[q * 4] = o;
            }
        }
    }
}

// ---------------- host orchestration ----------------
extern "C" void kernel_launch(void* const* d_in, const int* in_sizes, int n_in,
                              void* d_out, int out_size) {
    const float* s0r   = (const float*)d_in[0];
    const float* s1r   = (const float*)d_in[1];
    const float* gates = (const float*)d_in[2];
    const float* pre0  = (const float*)d_in[3];
    const float* pre1  = (const float*)d_in[4];
    const float* s3d1  = (const float*)d_in[5];
    const float* s3p1  = (const float*)d_in[6];
    const float* s3d2  = (const float*)d_in[7];
    const float* s3p2  = (const float*)d_in[8];
    const float* s5d1  = (const float*)d_in[9];
    const float* s5p1  = (const float*)d_in[10];
    const float* s5d2  = (const float*)d_in[11];
    const float* s5p2  = (const float*)d_in[12];
    const float* d3d   = (const float*)d_in[13];
    const float* d3p   = (const float*)d_in[14];
    const float* d5d   = (const float*)d_in[15];
    const float* d5p   = (const float*)d_in[16];
    float* out = (float*)d_out;

    float *ps0, *ps1, *pt, *pu, *pp;
    cudaGetSymbolAddress((void**)&ps0, g_s0);
    cudaGetSymbolAddress((void**)&ps1, g_s1);
    cudaGetSymbolAddress((void**)&pt,  g_t);
    cudaGetSymbolAddress((void**)&pu,  g_u);
    cudaGetSymbolAddress((void**)&pp,  g_pw);

    gate_kernel<<<2, 256>>>(gates, pp);

    // preprocess: s0/s1 -> states 0/1 (ReLU -> 1x1 conv 512->128 -> BN)
    {
        GemmArgs pa = {};
        pa.K = CIN; pa.reluB = 1;
        pa.A[0] = pre0; pa.B[0] = s0r; pa.Cp[0] = ps0; pa.P[0] = nullptr;
        pa.cscale[0] = BNS; pa.bsB[0] = (long)CIN * HW; pa.bsC[0] = PLANE;
        pa.A[1] = pre1; pa.B[1] = s1r; pa.Cp[1] = ps1; pa.P[1] = nullptr;
        pa.cscale[1] = BNS; pa.bsB[1] = (long)CIN * HW; pa.bsC[1] = PLANE;
        gemm256<<<dim3(4, NB, 2), 256>>>(pa);
    }

    struct StateDesc { float* p; long bs; };
    StateDesc st[6] = {
        {ps0, (long)PLANE}, {ps1, (long)PLANE},
        {out,             512L * HW}, {out + PLANE,     512L * HW},
        {out + 2 * PLANE, 512L * HW}, {out + 3 * PLANE, 512L * HW}
    };

    const float* dw1w[4]  = {s3d1, s5d1, d3d, d5d};
    const long   dw1sz[4] = {9, 25, 9, 25};
    const int    dwk[4]   = {3, 5, 3, 5};
    const int    dwdil[4] = {1, 1, 2, 2};
    const float* pw1w[4]  = {s3p1, s5p1, d3p, d5p};

    int offset = 0;
    for (int i = 0; i < 4; i++) {
        int nj = 2 + i;
        StateDesc dst = st[2 + i];

        // pools + skip, all j in one launch
        PoolArgs pa = {};
        for (int j = 0; j < nj; j++) {
            pa.X[j] = st[j].p; pa.bsX[j] = st[j].bs;
            pa.P[j] = pp + (long)(offset + j) * NB * 8;
        }
        pa.O = dst.p; pa.bsO = dst.bs; pa.nj = nj;
        pool_kernel<<<dim3(CC, NB), 256>>>(pa);

        // dw1: all (j, branch)
        DwArgs d1 = {};
        for (int j = 0; j < nj; j++) {
            int m = offset + j;
            const float* gp = pp + (long)m * NB * 8;
            for (int br = 0; br < 4; br++) {
                int e = j * 4 + br;
                d1.X[e] = st[j].p; d1.bsX[e] = st[j].bs;
                d1.W[e] = dw1w[br] + (long)m * CC * dw1sz[br];
                d1.Y[e] = pt + (long)e * NBPLANE;
                d1.P[e] = gp + 4 + br;
                d1.ks[e] = dwk[br]; d1.dil[e] = dwdil[br];
            }
        }
        dw_kernel<<<dim3(CC, NB, nj * 4), 256>>>(d1);

        // gemm1: sep pw1 -> u (store), dil pw -> dst (scaled atomic accumulate)
        GemmArgs g1 = {};
        g1.K = CC; g1.reluB = 0;
        for (int j = 0; j < nj; j++) {
            int m = offset + j;
            const float* gp = pp + (long)m * NB * 8;
            for (int br = 0; br < 4; br++) {
                int e = j * 4 + br;
                g1.A[e] = pw1w[br] + (long)m * CC * CC;
                g1.B[e] = pt + (long)e * NBPLANE;
                g1.P[e] = gp + 4 + br;
                g1.cscale[e] = BNS;
                g1.bsB[e] = PLANE;
                if (br < 2) {
                    g1.Cp[e] = pu + (long)(j * 2 + br) * NBPLANE;
                    g1.byP[e] = 0; g1.accum[e] = 0; g1.bsC[e] = PLANE;
                } else {
                    g1.Cp[e] = dst.p;
                    g1.byP[e] = 1; g1.accum[e] = 1; g1.bsC[e] = dst.bs;
                }
            }
        }
        gemm256<<<dim3(4, NB, nj * 4), 256>>>(g1);

        // dw2: sep3_dw2 / sep5_dw2 on relu(u); outputs alias pt slots (already consumed)
        DwArgs d2 = {};
        for (int j = 0; j < nj; j++) {
            int m = offset + j;
            const float* gp = pp + (long)m * NB * 8;
            for (int br = 0; br < 2; br++) {
                int e = j * 2 + br;
                d2.X[e] = pu + (long)e * NBPLANE; d2.bsX[e] = PLANE;
                d2.W[e] = (br == 0 ? s3d2 + (long)m * CC * 9 : s5d2 + (long)m * CC * 25);
                d2.Y[e] = pt + (long)(j * 4 + br) * NBPLANE;
                d2.P[e] = gp + 4 + br;
                d2.ks[e] = (br == 0 ? 3 : 5); d2.dil[e] = 1;
            }
        }
        dw_kernel<<<dim3(CC, NB, nj * 2), 256>>>(d2);

        // gemm2: sep pw2 -> dst (scaled atomic accumulate)
        GemmArgs g2 = {};
        g2.K = CC; g2.reluB = 0;
        for (int j = 0; j < nj; j++) {
            int m = offset + j;
            const float* gp = pp + (long)m * NB * 8;
            for (int br = 0; br < 2; br++) {
                int e = j * 2 + br;
                g2.A[e] = (br == 0 ? s3p2 + (long)m * CC * CC : s5p2 + (long)m * CC * CC);
                g2.B[e] = pt + (long)(j * 4 + br) * NBPLANE;
                g2.Cp[e] = dst.p;
                g2.P[e] = gp + 4 + br;
                g2.cscale[e] = BNS; g2.byP[e] = 1; g2.accum[e] = 1;
                g2.bsB[e] = PLANE; g2.bsC[e] = dst.bs;
            }
        }
        gemm256<<<dim3(4, NB, nj * 2), 256>>>(g2);

        offset += nj;
    }
}

// round 8
// speedup vs baseline: 2.0991x; 2.0991x over previous
#include <cuda_runtime.h>
#include <cuda_bf16.h>
#include <cstdint>

// ---------------- problem constants ----------------
#define NB    32          // batch
#define CC    128         // cell channels
#define CIN   512         // input channels
#define HW    1024        // 32*32
#define PLANE (CC*HW)     // 131072 floats per (batch, state)
#define NBPLANE (NB*PLANE)
#define NMIX  14
#define BNS   0.9999950000374997f   // 1/sqrt(1+1e-5)

// ---------------- device scratch (static, allocation-free) ----------------
__device__ __align__(16) float g_s0[NBPLANE];
__device__ __align__(16) float g_s1[NBPLANE];
__device__ __align__(16) float g_t[20L * NBPLANE];   // dw1 outputs (and dw2 outputs, aliased)
__device__ __align__(16) float g_u[10L * NBPLANE];   // sep pw1 outputs
__device__ __align__(16) float g_pw[NMIX * NB * 8];

// ---------------- gate kernel: top-2 + masked softmax ----------------
__global__ void gate_kernel(const float* __restrict__ gates, float* __restrict__ P) {
    int idx = blockIdx.x * blockDim.x + threadIdx.x;
    if (idx >= NMIX * NB) return;
    const float* g = gates + idx * 8;
    float gv[8];
#pragma unroll
    for (int j = 0; j < 8; j++) gv[j] = g[j];
    bool sel[8] = {false, false, false, false, false, false, false, false};
    for (int t = 0; t < 2; t++) {      // top = 2 fixed by setup_inputs
        int best = -1; float bv = -3.4e38f;
#pragma unroll
        for (int j = 0; j < 8; j++)
            if (!sel[j] && gv[j] > bv) { bv = gv[j]; best = j; }
        sel[best] = true;
    }
    float mx = -3.4e38f;
#pragma unroll
    for (int j = 0; j < 8; j++) if (sel[j]) mx = fmaxf(mx, gv[j]);
    float e[8]; float s = 0.f;
#pragma unroll
    for (int j = 0; j < 8; j++) { e[j] = sel[j] ? expf(gv[j] - mx) : 0.f; s += e[j]; }
#pragma unroll
    for (int j = 0; j < 8; j++) P[idx * 8 + j] = e[j] / s;
}

// ---------------- fused pool/skip kernel (loops over all j of a step) ----------------
struct PoolArgs {
    const float* X[5]; long bsX[5];
    const float* P[5];
    float* O; long bsO;
    int nj;
};

__global__ __launch_bounds__(256) void pool_kernel(PoolArgs pa) {
    int c = blockIdx.x, b = blockIdx.y, tid = threadIdx.x;
    __shared__ float st[1024];
    float acc[4] = {0.f, 0.f, 0.f, 0.f};
    for (int j = 0; j < pa.nj; j++) {
        const float* pj = pa.P[j] + b * 8;
        float p1 = pj[1], p2 = pj[2], p3 = pj[3];
        if (p1 == 0.f && p2 == 0.f && p3 == 0.f) continue;   // uniform over block
        __syncthreads();
        const float* xp = pa.X[j] + (long)b * pa.bsX[j] + c * HW;
        for (int i = tid; i < 1024; i += 256) st[i] = xp[i];
        __syncthreads();
#pragma unroll
        for (int q = 0; q < 4; q++) {
            int px = tid + q * 256;
            int y = px >> 5, x = px & 31;
            float mx = -3.4e38f, s = 0.f; int cnt = 0;
#pragma unroll
            for (int dy = -1; dy <= 1; dy++) {
                int yy = y + dy;
                if (yy < 0 || yy > 31) continue;
#pragma unroll
                for (int dx = -1; dx <= 1; dx++) {
                    int xx = x + dx;
                    if (xx < 0 || xx > 31) continue;
                    float v = st[yy * 32 + xx];
                    mx = fmaxf(mx, v); s += v; cnt++;
                }
            }
            acc[q] += p1 * (BNS * mx) + p2 * (BNS * (s / (float)cnt)) + p3 * st[px];
        }
    }
    float* op = pa.O + (long)b * pa.bsO + c * HW;
#pragma unroll
    for (int q = 0; q < 4; q++) op[tid + q * 256] = acc[q];   // sole writer pre-GEMM
}

// ---------------- fused multi-entry depthwise conv ----------------
struct DwArgs {
    const float* X[20]; long bsX[20];
    const float* W[20];
    float*       Y[20];
    const float* P[20];
    int ks[20], dil[20];
};

template<int KS, int DIL, int PAD>
__device__ __forceinline__ void dw_inner(const float* __restrict__ st,
                                         const float* __restrict__ w,
                                         float* __restrict__ yp, int tid)
{
    for (int px = tid; px < 1024; px += 256) {
        int y = px >> 5, x = px & 31;
        const float* base = st + (y + 4 - PAD) * 40 + (x + 4 - PAD);
        float acc = 0.f;
#pragma unroll
        for (int i = 0; i < KS; i++)
#pragma unroll
            for (int j = 0; j < KS; j++)
                acc += w[i * KS + j] * base[i * DIL * 40 + j * DIL];
        yp[px] = acc;
    }
}

__global__ __launch_bounds__(256) void dw_kernel(DwArgs da) {
    int e = blockIdx.z, b = blockIdx.y, c = blockIdx.x;
    if (da.P[e][b * 8] == 0.f) return;
    __shared__ float st[1600];  // 40x40, relu(x) with zero halo (max pad 4)
    int tid = threadIdx.x;
    for (int i = tid; i < 1600; i += 256) st[i] = 0.f;
    __syncthreads();
    const float* xp = da.X[e] + (long)b * da.bsX[e] + c * HW;
    for (int i = tid; i < 1024; i += 256) {
        int y = i >> 5, x = i & 31;
        st[(y + 4) * 40 + x + 4] = fmaxf(xp[i], 0.f);
    }
    __syncthreads();
    int ks = da.ks[e];
    int ksz = ks * ks;
    const float* wp = da.W[e] + c * ksz;
    float w[25];
#pragma unroll
    for (int i = 0; i < 25; i++) w[i] = (i < ksz) ? wp[i] : 0.f;
    float* yp = da.Y[e] + (long)b * PLANE + c * HW;
    int dil = da.dil[e];
    if (ks == 3 && dil == 1)      dw_inner<3,1,1>(st, w, yp, tid);
    else if (ks == 5 && dil == 1) dw_inner<5,1,2>(st, w, yp, tid);
    else if (ks == 3)             dw_inner<3,2,2>(st, w, yp, tid);
    else                          dw_inner<5,2,4>(st, w, yp, tid);
}

// ---------------- tensor-core GEMM (bf16 hi/lo split, fp32 accumulate) ----------------
// C[128(M) x 1024(N)] = A[128 x K] * B[K x 1024] per (entry, batch).
// Block: 256 thr = 8 warps (4M x 2N), tile 128(M) x 128(N), k-step 16.
// Split: x = hi + lo (bf16); C += A_hi*B_hi + A_lo*B_hi + A_hi*B_lo.
struct GemmArgs {
    const float* A[20];
    const float* B[20];
    float*       Cp[20];
    const float* P[20];
    float        cscale[20];
    int          byP[20];
    int          accum[20];
    long         bsB[20];
    long         bsC[20];
    int          K;
    int          reluB;
};

__device__ __forceinline__ void relu4(float4& v) {
    v.x = fmaxf(v.x, 0.f); v.y = fmaxf(v.y, 0.f);
    v.z = fmaxf(v.z, 0.f); v.w = fmaxf(v.w, 0.f);
}

__device__ __forceinline__ uint32_t packbf2(float e0, float e1) {
    // low half <- e0, high half <- e1 (PTX: first src -> upper)
    uint32_t r;
    asm("cvt.rn.bf16x2.f32 %0, %1, %2;" : "=r"(r) : "f"(e1), "f"(e0));
    return r;
}

// convert float4 pair-wise into (hi, lo) packed bf16x2 words
__device__ __forceinline__ void split4(float4 v, uint32_t& h0, uint32_t& h1,
                                       uint32_t& l0, uint32_t& l1) {
    h0 = packbf2(v.x, v.y);
    h1 = packbf2(v.z, v.w);
    float rx = v.x - __uint_as_float(h0 << 16);
    float ry = v.y - __uint_as_float(h0 & 0xffff0000u);
    float rz = v.z - __uint_as_float(h1 << 16);
    float rw = v.w - __uint_as_float(h1 & 0xffff0000u);
    l0 = packbf2(rx, ry);
    l1 = packbf2(rz, rw);
}

__device__ __forceinline__ void ldsm4(uint32_t* d, uint32_t addr) {
    asm volatile("ldmatrix.sync.aligned.m8n8.x4.shared.b16 {%0,%1,%2,%3}, [%4];"
                 : "=r"(d[0]), "=r"(d[1]), "=r"(d[2]), "=r"(d[3]) : "r"(addr));
}
__device__ __forceinline__ void ldsm4t(uint32_t* d, uint32_t addr) {
    asm volatile("ldmatrix.sync.aligned.m8n8.x4.trans.shared.b16 {%0,%1,%2,%3}, [%4];"
                 : "=r"(d[0]), "=r"(d[1]), "=r"(d[2]), "=r"(d[3]) : "r"(addr));
}
__device__ __forceinline__ void mma16816(float* c, const uint32_t* a,
                                         uint32_t b0, uint32_t b1) {
    asm volatile("mma.sync.aligned.m16n8k16.row.col.f32.bf16.bf16.f32 "
                 "{%0,%1,%2,%3}, {%4,%5,%6,%7}, {%8,%9}, {%0,%1,%2,%3};"
                 : "+f"(c[0]), "+f"(c[1]), "+f"(c[2]), "+f"(c[3])
                 : "r"(a[0]), "r"(a[1]), "r"(a[2]), "r"(a[3]), "r"(b0), "r"(b1));
}

#define A_LD 24    // halfs per A smem row (16 data + pad, 48B: conflict-free ldmatrix)
#define B_LD 136   // halfs per B smem row (128 data + pad, 272B: conflict-free ldmatrix)

__global__ __launch_bounds__(256) void gemm_mma(GemmArgs ga) {
    int e = blockIdx.z, b = blockIdx.y;
    const float* gp = ga.P[e];
    float pv = 1.f;
    if (gp) { pv = gp[b * 8]; if (pv == 0.f) return; }
    float scale = ga.cscale[e] * (ga.byP[e] ? pv : 1.f);
    const int K = ga.K;
    const int reluB = ga.reluB;

    __shared__ __align__(16) __nv_bfloat16 As[2][128][A_LD];
    __shared__ __align__(16) __nv_bfloat16 Bs[2][16][B_LD];

    int tid  = threadIdx.x;
    int lane = tid & 31, w = tid >> 5;
    int wm = (w & 3) * 32;        // warp M origin (2 x m16)
    int wn = (w >> 2) * 64;       // warp N origin (8 x n8)

    // loader mapping
    int am = tid >> 1, ak = (tid & 1) * 8;     // A: row am, 8 k-floats
    int bk = tid >> 4, bc = (tid & 15) * 8;    // B: k-row bk, 8 n-floats

    const float* Aptr = ga.A[e] + (long)am * K + ak;
    const float* Bptr = ga.B[e] + (long)b * ga.bsB[e] + blockIdx.x * 128
                        + (long)bk * HW + bc;
    float* Cm = ga.Cp[e] + (long)b * ga.bsC[e] + blockIdx.x * 128;

    // ldmatrix lane addressing (same row/col pattern for A and B-trans)
    int r8   = lane & 7, quad = lane >> 3;
    int lrow = r8 + (quad & 1) * 8;
    int lcol = (quad >> 1) * 8;

    uint32_t asBase = (uint32_t)__cvta_generic_to_shared(&As[0][0][0]);
    uint32_t bsBase = (uint32_t)__cvta_generic_to_shared(&Bs[0][0][0]);
    uint32_t aAddr[2][2], bAddr[2][4];
#pragma unroll
    for (int p = 0; p < 2; p++) {
#pragma unroll
        for (int mt = 0; mt < 2; mt++)
            aAddr[p][mt] = asBase + ((p * 128 + wm + mt * 16 + lrow) * A_LD + lcol) * 2;
#pragma unroll
        for (int i = 0; i < 4; i++)
            bAddr[p][i] = bsBase + ((p * 16 + lrow) * B_LD + wn + i * 16 + lcol) * 2;
    }

    float acc[2][8][4];
#pragma unroll
    for (int mt = 0; mt < 2; mt++)
#pragma unroll
        for (int nt = 0; nt < 8; nt++)
#pragma unroll
            for (int q = 0; q < 4; q++) acc[mt][nt][q] = 0.f;

    // prefetch step 0
    float4 ra0 = *(const float4*)(Aptr);
    float4 ra1 = *(const float4*)(Aptr + 4);
    float4 rb0 = *(const float4*)(Bptr);
    float4 rb1 = *(const float4*)(Bptr + 4);

    const int T = K >> 4;
    for (int t = 0; t < T; t++) {
        if (reluB) { relu4(rb0); relu4(rb1); }
        // convert + store A (hi plane 0, lo plane 1)
        {
            uint32_t h0, h1, h2, h3, l0, l1, l2, l3;
            split4(ra0, h0, h1, l0, l1);
            split4(ra1, h2, h3, l2, l3);
            *(uint4*)&As[0][am][ak] = make_uint4(h0, h1, h2, h3);
            *(uint4*)&As[1][am][ak] = make_uint4(l0, l1, l2, l3);
        }
        {
            uint32_t h0, h1, h2, h3, l0, l1, l2, l3;
            split4(rb0, h0, h1, l0, l1);
            split4(rb1, h2, h3, l2, l3);
            *(uint4*)&Bs[0][bk][bc] = make_uint4(h0, h1, h2, h3);
            *(uint4*)&Bs[1][bk][bc] = make_uint4(l0, l1, l2, l3);
        }
        __syncthreads();

        bool more = (t + 1 < T);
        if (more) {
            ra0 = *(const float4*)(Aptr + (t + 1) * 16);
            ra1 = *(const float4*)(Aptr + (t + 1) * 16 + 4);
            const float* bp = Bptr + (long)(t + 1) * 16 * HW;
            rb0 = *(const float4*)(bp);
            rb1 = *(const float4*)(bp + 4);
        }

        uint32_t afr[2][2][4];
        uint32_t bfr[2][4][4];
#pragma unroll
        for (int p = 0; p < 2; p++) {
#pragma unroll
            for (int mt = 0; mt < 2; mt++) ldsm4(afr[p][mt], aAddr[p][mt]);
#pragma unroll
            for (int i = 0; i < 4; i++)    ldsm4t(bfr[p][i], bAddr[p][i]);
        }

        // three split terms: (A_hi,B_hi), (A_lo,B_hi), (A_hi,B_lo)
#pragma unroll
        for (int combo = 0; combo < 3; combo++) {
            int ap = (combo == 1) ? 1 : 0;
            int bp = (combo == 2) ? 1 : 0;
#pragma unroll
            for (int mt = 0; mt < 2; mt++)
#pragma unroll
                for (int nt = 0; nt < 8; nt++) {
                    int i = nt >> 1, po = (nt & 1) * 2;
                    mma16816(acc[mt][nt], afr[ap][mt], bfr[bp][i][po], bfr[bp][i][po + 1]);
                }
        }
        __syncthreads();
    }

    // epilogue
    int g = lane >> 2, tig = lane & 3;
    if (ga.accum[e]) {
#pragma unroll
        for (int mt = 0; mt < 2; mt++)
#pragma unroll
            for (int nt = 0; nt < 8; nt++) {
                int row = wm + mt * 16 + g;
                int col = wn + nt * 8 + tig * 2;
                float* p0 = Cm + (long)row * HW + col;
                float* p1 = p0 + 8 * HW;
                atomicAdd(&p0[0], scale * acc[mt][nt][0]);
                atomicAdd(&p0[1], scale * acc[mt][nt][1]);
                atomicAdd(&p1[0], scale * acc[mt][nt][2]);
                atomicAdd(&p1[1], scale * acc[mt][nt][3]);
            }
    } else {
#pragma unroll
        for (int mt = 0; mt < 2; mt++)
#pragma unroll
            for (int nt = 0; nt < 8; nt++) {
                int row = wm + mt * 16 + g;
                int col = wn + nt * 8 + tig * 2;
                float* p0 = Cm + (long)row * HW + col;
                float* p1 = p0 + 8 * HW;
                *(float2*)p0 = make_float2(scale * acc[mt][nt][0], scale * acc[mt][nt][1]);
                *(float2*)p1 = make_float2(scale * acc[mt][nt][2], scale * acc[mt][nt][3]);
            }
    }
}

// ---------------- host orchestration ----------------
extern "C" void kernel_launch(void* const* d_in, const int* in_sizes, int n_in,
                              void* d_out, int out_size) {
    const float* s0r   = (const float*)d_in[0];
    const float* s1r   = (const float*)d_in[1];
    const float* gates = (const float*)d_in[2];
    const float* pre0  = (const float*)d_in[3];
    const float* pre1  = (const float*)d_in[4];
    const float* s3d1  = (const float*)d_in[5];
    const float* s3p1  = (const float*)d_in[6];
    const float* s3d2  = (const float*)d_in[7];
    const float* s3p2  = (const float*)d_in[8];
    const float* s5d1  = (const float*)d_in[9];
    const float* s5p1  = (const float*)d_in[10];
    const float* s5d2  = (const float*)d_in[11];
    const float* s5p2  = (const float*)d_in[12];
    const float* d3d   = (const float*)d_in[13];
    const float* d3p   = (const float*)d_in[14];
    const float* d5d   = (const float*)d_in[15];
    const float* d5p   = (const float*)d_in[16];
    float* out = (float*)d_out;

    float *ps0, *ps1, *pt, *pu, *pp;
    cudaGetSymbolAddress((void**)&ps0, g_s0);
    cudaGetSymbolAddress((void**)&ps1, g_s1);
    cudaGetSymbolAddress((void**)&pt,  g_t);
    cudaGetSymbolAddress((void**)&pu,  g_u);
    cudaGetSymbolAddress((void**)&pp,  g_pw);

    gate_kernel<<<2, 256>>>(gates, pp);

    // preprocess: s0/s1 -> states 0/1 (ReLU -> 1x1 conv 512->128 -> BN)
    {
        GemmArgs pa = {};
        pa.K = CIN; pa.reluB = 1;
        pa.A[0] = pre0; pa.B[0] = s0r; pa.Cp[0] = ps0; pa.P[0] = nullptr;
        pa.cscale[0] = BNS; pa.bsB[0] = (long)CIN * HW; pa.bsC[0] = PLANE;
        pa.A[1] = pre1; pa.B[1] = s1r; pa.Cp[1] = ps1; pa.P[1] = nullptr;
        pa.cscale[1] = BNS; pa.bsB[1] = (long)CIN * HW; pa.bsC[1] = PLANE;
        gemm_mma<<<dim3(8, NB, 2), 256>>>(pa);
    }

    struct StateDesc { float* p; long bs; };
    StateDesc st[6] = {
        {ps0, (long)PLANE}, {ps1, (long)PLANE},
        {out,             512L * HW}, {out + PLANE,     512L * HW},
        {out + 2 * PLANE, 512L * HW}, {out + 3 * PLANE, 512L * HW}
    };

    const float* dw1w[4]  = {s3d1, s5d1, d3d, d5d};
    const long   dw1sz[4] = {9, 25, 9, 25};
    const int    dwk[4]   = {3, 5, 3, 5};
    const int    dwdil[4] = {1, 1, 2, 2};
    const float* pw1w[4]  = {s3p1, s5p1, d3p, d5p};

    int offset = 0;
    for (int i = 0; i < 4; i++) {
        int nj = 2 + i;
        StateDesc dst = st[2 + i];

        // pools + skip, all j in one launch
        PoolArgs pa = {};
        for (int j = 0; j < nj; j++) {
            pa.X[j] = st[j].p; pa.bsX[j] = st[j].bs;
            pa.P[j] = pp + (long)(offset + j) * NB * 8;
        }
        pa.O = dst.p; pa.bsO = dst.bs; pa.nj = nj;
        pool_kernel<<<dim3(CC, NB), 256>>>(pa);

        // dw1: all (j, branch)
        DwArgs d1 = {};
        for (int j = 0; j < nj; j++) {
            int m = offset + j;
            const float* gp = pp + (long)m * NB * 8;
            for (int br = 0; br < 4; br++) {
                int e = j * 4 + br;
                d1.X[e] = st[j].p; d1.bsX[e] = st[j].bs;
                d1.W[e] = dw1w[br] + (long)m * CC * dw1sz[br];
                d1.Y[e] = pt + (long)e * NBPLANE;
                d1.P[e] = gp + 4 + br;
                d1.ks[e] = dwk[br]; d1.dil[e] = dwdil[br];
            }
        }
        dw_kernel<<<dim3(CC, NB, nj * 4), 256>>>(d1);

        // gemm1: sep pw1 -> u (store), dil pw -> dst (scaled atomic accumulate)
        GemmArgs g1 = {};
        g1.K = CC; g1.reluB = 0;
        for (int j = 0; j < nj; j++) {
            int m = offset + j;
            const float* gp = pp + (long)m * NB * 8;
            for (int br = 0; br < 4; br++) {
                int e = j * 4 + br;
                g1.A[e] = pw1w[br] + (long)m * CC * CC;
                g1.B[e] = pt + (long)e * NBPLANE;
                g1.P[e] = gp + 4 + br;
                g1.cscale[e] = BNS;
                g1.bsB[e] = PLANE;
                if (br < 2) {
                    g1.Cp[e] = pu + (long)(j * 2 + br) * NBPLANE;
                    g1.byP[e] = 0; g1.accum[e] = 0; g1.bsC[e] = PLANE;
                } else {
                    g1.Cp[e] = dst.p;
                    g1.byP[e] = 1; g1.accum[e] = 1; g1.bsC[e] = dst.bs;
                }
            }
        }
        gemm_mma<<<dim3(8, NB, nj * 4), 256>>>(g1);

        // dw2: sep3_dw2 / sep5_dw2 on relu(u); outputs alias pt slots (already consumed)
        DwArgs d2 = {};
        for (int j = 0; j < nj; j++) {
            int m = offset + j;
            const float* gp = pp + (long)m * NB * 8;
            for (int br = 0; br < 2; br++) {
                int e = j * 2 + br;
                d2.X[e] = pu + (long)e * NBPLANE; d2.bsX[e] = PLANE;
                d2.W[e] = (br == 0 ? s3d2 + (long)m * CC * 9 : s5d2 + (long)m * CC * 25);
                d2.Y[e] = pt + (long)(j * 4 + br) * NBPLANE;
                d2.P[e] = gp + 4 + br;
                d2.ks[e] = (br == 0 ? 3 : 5); d2.dil[e] = 1;
            }
        }
        dw_kernel<<<dim3(CC, NB, nj * 2), 256>>>(d2);

        // gemm2: sep pw2 -> dst (scaled atomic accumulate)
        GemmArgs g2 = {};
        g2.K = CC; g2.reluB = 0;
        for (int j = 0; j < nj; j++) {
            int m = offset + j;
            const float* gp = pp + (long)m * NB * 8;
            for (int br = 0; br < 2; br++) {
                int e = j * 2 + br;
                g2.A[e] = (br == 0 ? s3p2 + (long)m * CC * CC : s5p2 + (long)m * CC * CC);
                g2.B[e] = pt + (long)(j * 4 + br) * NBPLANE;
                g2.Cp[e] = dst.p;
                g2.P[e] = gp + 4 + br;
                g2.cscale[e] = BNS; g2.byP[e] = 1; g2.accum[e] = 1;
                g2.bsB[e] = PLANE; g2.bsC[e] = dst.bs;
            }
        }
        gemm_mma<<<dim3(8, NB, nj * 2), 256>>>(g2);

        offset += nj;
    }
}